// round 1
// baseline (speedup 1.0000x reference)
#include <cuda_runtime.h>
#include <math.h>

// Problem constants
#define SEQ    512
#define BATCH  64
#define H2     1024
#define DIN    3072
#define KST    2048                 // state part of concat (2 layers * 1024)
#define M_ROWS (SEQ * BATCH)        // 32768 rows of enc, row m = s*64 + b
#define NT     16                   // 1024 / BN n-tiles in energy GEMM
#define KSPLIT 8                    // split-K for the tiny u GEMM

// GEMM tiling
#define BM 64
#define BN 64
#define BK 16

// Scratch (static device arrays; no dynamic allocation allowed)
__device__ __align__(16) float g_st[BATCH * KST];              // 512 KB: state flattened (b, l*1024+k)
__device__ __align__(16) float g_upart[KSPLIT * BATCH * H2];   // 2 MB: split-K partials of u
__device__ __align__(16) float g_u[BATCH * H2];                // 256 KB: u[b][h] = W1_state . st_b + b1
__device__ __align__(16) float g_epart[NT * M_ROWS];           // 2 MB: per-nTile partial energies

// ---------------------------------------------------------------------------
// Kernel 0: gather state (2,64,1024) -> st (64, 2048) with d = l*1024 + k
// ---------------------------------------------------------------------------
__global__ void buildSt(const float* __restrict__ state) {
    int idx = blockIdx.x * blockDim.x + threadIdx.x;   // 0 .. 131071
    int k = idx & 1023;
    int b = (idx >> 10) & 63;
    int l = idx >> 16;
    g_st[b * KST + l * 1024 + k] = state[(l * 64 + b) * 1024 + k];
}

// ---------------------------------------------------------------------------
// Kernel 1: u partials.  C[b][h] = sum_k st[b][k] * W1[h][k], split over K.
// grid = (16 nTiles, 8 ksplits), 256 threads.
// ---------------------------------------------------------------------------
__global__ void uGemm(const float* __restrict__ W1) {
    const int n0 = blockIdx.x * BN;
    const int ks = blockIdx.y;
    const int k0base = ks * (KST / KSPLIT);   // 256-wide K slice

    __shared__ float As[BK][BM];
    __shared__ float Bs[BK][BN];

    const int tid = threadIdx.x;
    const int tx = tid & 15;
    const int ty = tid >> 4;
    const int lrow = tid >> 2;          // 0..63
    const int lcol = (tid & 3) * 4;     // 0,4,8,12

    float acc[4][4];
#pragma unroll
    for (int i = 0; i < 4; i++)
#pragma unroll
        for (int j = 0; j < 4; j++) acc[i][j] = 0.f;

    for (int k0 = k0base; k0 < k0base + (KST / KSPLIT); k0 += BK) {
        float4 a = *(const float4*)&g_st[lrow * KST + k0 + lcol];
        float4 w = *(const float4*)&W1[(n0 + lrow) * DIN + k0 + lcol];
        As[lcol + 0][lrow] = a.x; As[lcol + 1][lrow] = a.y;
        As[lcol + 2][lrow] = a.z; As[lcol + 3][lrow] = a.w;
        Bs[lcol + 0][lrow] = w.x; Bs[lcol + 1][lrow] = w.y;
        Bs[lcol + 2][lrow] = w.z; Bs[lcol + 3][lrow] = w.w;
        __syncthreads();
#pragma unroll
        for (int kk = 0; kk < BK; kk++) {
            float4 av = *(const float4*)&As[kk][ty * 4];
            float4 bv = *(const float4*)&Bs[kk][tx * 4];
            acc[0][0] += av.x * bv.x; acc[0][1] += av.x * bv.y; acc[0][2] += av.x * bv.z; acc[0][3] += av.x * bv.w;
            acc[1][0] += av.y * bv.x; acc[1][1] += av.y * bv.y; acc[1][2] += av.y * bv.z; acc[1][3] += av.y * bv.w;
            acc[2][0] += av.z * bv.x; acc[2][1] += av.z * bv.y; acc[2][2] += av.z * bv.z; acc[2][3] += av.z * bv.w;
            acc[3][0] += av.w * bv.x; acc[3][1] += av.w * bv.y; acc[3][2] += av.w * bv.z; acc[3][3] += av.w * bv.w;
        }
        __syncthreads();
    }

    float* dst = &g_upart[ks * (BATCH * H2)];
#pragma unroll
    for (int i = 0; i < 4; i++) {
        int b = ty * 4 + i;
#pragma unroll
        for (int j = 0; j < 4; j++) {
            int h = n0 + tx * 4 + j;
            dst[b * H2 + h] = acc[i][j];
        }
    }
}

// ---------------------------------------------------------------------------
// Kernel 2: reduce split-K partials + bias -> g_u
// ---------------------------------------------------------------------------
__global__ void reduceU(const float* __restrict__ b1) {
    int idx = blockIdx.x * blockDim.x + threadIdx.x;   // 0 .. 65535
    int h = idx & 1023;
    float s = b1[h];
#pragma unroll
    for (int ks = 0; ks < KSPLIT; ks++) s += g_upart[ks * (BATCH * H2) + idx];
    g_u[idx] = s;
}

// ---------------------------------------------------------------------------
// Kernel 3 (the big one): per n-tile partial energy.
// z[m][n] = sum_k enc[m][k] * W1enc[n][k]     (m = s*64+b ; tile rows <=> b)
// epart[nTile][m] = sum_{n in tile} W2[n] * tanh(z + u[b][n])
// grid = (512 mTiles, 16 nTiles), 256 threads.
// ---------------------------------------------------------------------------
__global__ void energyGemm(const float* __restrict__ enc,
                           const float* __restrict__ W1,
                           const float* __restrict__ W2) {
    const int m0 = blockIdx.x * BM;     // rows m0..m0+63 : s = blockIdx.x, b = row
    const int n0 = blockIdx.y * BN;

    __shared__ float As[BK][BM];
    __shared__ float Bs[BK][BN];
    __shared__ float red[BM][16];

    const int tid = threadIdx.x;
    const int tx = tid & 15;
    const int ty = tid >> 4;
    const int lrow = tid >> 2;
    const int lcol = (tid & 3) * 4;

    float acc[4][4];
#pragma unroll
    for (int i = 0; i < 4; i++)
#pragma unroll
        for (int j = 0; j < 4; j++) acc[i][j] = 0.f;

    for (int k0 = 0; k0 < H2; k0 += BK) {
        float4 a = *(const float4*)&enc[(m0 + lrow) * H2 + k0 + lcol];
        float4 w = *(const float4*)&W1[(n0 + lrow) * DIN + KST + k0 + lcol];
        As[lcol + 0][lrow] = a.x; As[lcol + 1][lrow] = a.y;
        As[lcol + 2][lrow] = a.z; As[lcol + 3][lrow] = a.w;
        Bs[lcol + 0][lrow] = w.x; Bs[lcol + 1][lrow] = w.y;
        Bs[lcol + 2][lrow] = w.z; Bs[lcol + 3][lrow] = w.w;
        __syncthreads();
#pragma unroll
        for (int kk = 0; kk < BK; kk++) {
            float4 av = *(const float4*)&As[kk][ty * 4];
            float4 bv = *(const float4*)&Bs[kk][tx * 4];
            acc[0][0] += av.x * bv.x; acc[0][1] += av.x * bv.y; acc[0][2] += av.x * bv.z; acc[0][3] += av.x * bv.w;
            acc[1][0] += av.y * bv.x; acc[1][1] += av.y * bv.y; acc[1][2] += av.y * bv.z; acc[1][3] += av.y * bv.w;
            acc[2][0] += av.z * bv.x; acc[2][1] += av.z * bv.y; acc[2][2] += av.z * bv.z; acc[2][3] += av.z * bv.w;
            acc[3][0] += av.w * bv.x; acc[3][1] += av.w * bv.y; acc[3][2] += av.w * bv.z; acc[3][3] += av.w * bv.w;
        }
        __syncthreads();
    }

    // Epilogue: tanh + W2 dot, reduce the 16 column-groups per row.
    float w2f[4];
    int nbase = n0 + tx * 4;
#pragma unroll
    for (int j = 0; j < 4; j++) w2f[j] = W2[nbase + j];

#pragma unroll
    for (int i = 0; i < 4; i++) {
        int row = ty * 4 + i;            // == b
        const float* urow = &g_u[row * H2 + nbase];
        float p = 0.f;
#pragma unroll
        for (int j = 0; j < 4; j++) {
            float z = tanhf(acc[i][j] + urow[j]);
            p += z * w2f[j];
        }
        red[row][tx] = p;
    }
    __syncthreads();

    if (tid < BM) {
        float s = 0.f;
#pragma unroll
        for (int j = 0; j < 16; j++) s += red[tid][j];
        g_epart[blockIdx.y * M_ROWS + m0 + tid] = s;
    }
}

// ---------------------------------------------------------------------------
// Kernel 4: softmax over s per batch.  Writes alpha into d_out[65536 + b*512 + s].
// (b2 is a constant shift -> softmax invariant -> dropped.)
// ---------------------------------------------------------------------------
__global__ void softmaxK(float* __restrict__ out) {
    int b = blockIdx.x;
    int s = threadIdx.x;   // 512 threads
    float e = 0.f;
#pragma unroll
    for (int nt = 0; nt < NT; nt++) e += g_epart[nt * M_ROWS + s * 64 + b];

    __shared__ float sm[512];
    sm[s] = e;
    __syncthreads();
    for (int off = 256; off > 0; off >>= 1) {
        if (s < off) sm[s] = fmaxf(sm[s], sm[s + off]);
        __syncthreads();
    }
    float mx = sm[0];
    __syncthreads();

    float ex = expf(e - mx);
    sm[s] = ex;
    __syncthreads();
    for (int off = 256; off > 0; off >>= 1) {
        if (s < off) sm[s] += sm[s + off];
        __syncthreads();
    }
    float total = sm[0];

    out[BATCH * H2 + b * SEQ + s] = ex / total;
}

// ---------------------------------------------------------------------------
// Kernel 5: context[b][h] = sum_s alpha[b][s] * enc[s][b][h]
// grid = (4 h-chunks, 64 b), 256 threads.
// ---------------------------------------------------------------------------
__global__ void contextK(const float* __restrict__ enc, float* __restrict__ out) {
    int b = blockIdx.y;
    int h = blockIdx.x * 256 + threadIdx.x;

    __shared__ float sa[512];
    sa[threadIdx.x]       = out[BATCH * H2 + b * SEQ + threadIdx.x];
    sa[threadIdx.x + 256] = out[BATCH * H2 + b * SEQ + threadIdx.x + 256];
    __syncthreads();

    const float* base = enc + b * H2 + h;
    float a0 = 0.f, a1 = 0.f, a2 = 0.f, a3 = 0.f;
#pragma unroll 4
    for (int s = 0; s < SEQ; s += 4) {
        a0 += sa[s + 0] * base[(size_t)(s + 0) * (BATCH * H2)];
        a1 += sa[s + 1] * base[(size_t)(s + 1) * (BATCH * H2)];
        a2 += sa[s + 2] * base[(size_t)(s + 2) * (BATCH * H2)];
        a3 += sa[s + 3] * base[(size_t)(s + 3) * (BATCH * H2)];
    }
    out[b * H2 + h] = (a0 + a1) + (a2 + a3);
}

// ---------------------------------------------------------------------------
extern "C" void kernel_launch(void* const* d_in, const int* in_sizes, int n_in,
                              void* d_out, int out_size) {
    const float* state = (const float*)d_in[0];   // (2, 64, 1024)
    const float* enc   = (const float*)d_in[1];   // (512, 64, 1024)
    const float* W1    = (const float*)d_in[2];   // (1024, 3072)
    const float* b1    = (const float*)d_in[3];   // (1024,)
    const float* W2    = (const float*)d_in[4];   // (1, 1024)
    // d_in[5] = b2 : softmax-invariant, unused.
    float* out = (float*)d_out;                   // [0,65536): context ; [65536,98304): alpha

    buildSt<<<512, 256>>>(state);
    uGemm<<<dim3(16, KSPLIT), 256>>>(W1);
    reduceU<<<256, 256>>>(b1);
    energyGemm<<<dim3(M_ROWS / BM, NT), 256>>>(enc, W1, W2);
    softmaxK<<<BATCH, 512>>>(out);
    contextK<<<dim3(4, BATCH), 256>>>(enc, out);
}